// round 5
// baseline (speedup 1.0000x reference)
#include <cuda_runtime.h>
#include <math.h>
#include <stdint.h>

// ---------------------------------------------------------------------------
// StarTransformerLayer: B=8, L=4096, H=256, NH=8, HD=32, 2 iterations.
// Key-sharing: sat keys {before,cur,after,x,cexp} reuse one projected K/V of
// cur (+x once, +center 8 rows); rel keys [center; cur] likewise.
// R3: 14 big GEMMs on tensor cores via 3xTF32 split mma.sync.
// R4: batch independent GEMMs sharing X into one launch (blockIdx.z selects
//     W/bias/Y) to fix 1.73-wave quantization; merge small_proj launches.
// ---------------------------------------------------------------------------

#define DEV_INLINE __device__ __forceinline__

constexpr int B_  = 8;
constexpr int L_  = 4096;
constexpr int H_  = 256;
constexpr int NH_ = 8;
constexpr int HD_ = 32;
constexpr int M_  = B_ * L_;          // 32768 tokens
constexpr float SCALE_ = 0.17677669529663687f;   // 1/sqrt(32)
constexpr float LN_EPS_ = 1e-12f;

constexpr int RSEG_   = 16;                       // rel-attn key segments
constexpr int SEGLEN_ = (L_ + 1 + RSEG_ - 1) / RSEG_;  // 257

// ------------------------- scratch (device globals) ------------------------
__device__ float g_cur[(size_t)M_ * H_];
__device__ float g_Kx [(size_t)M_ * H_];
__device__ float g_Vx [(size_t)M_ * H_];
__device__ float g_Q  [(size_t)M_ * H_];
__device__ float g_K  [(size_t)M_ * H_];   // reused: sat Kc, then rel K
__device__ float g_V  [(size_t)M_ * H_];   // reused: sat Vc, then rel V
__device__ float g_ctx[(size_t)M_ * H_];
__device__ float g_tmp[(size_t)M_ * H_];

__device__ float g_center[B_ * H_];
__device__ float g_cpart [B_ * 32 * H_];
__device__ float g_Kcen  [B_ * H_];
__device__ float g_Vcen  [B_ * H_];
__device__ float g_Qr    [B_ * H_];
__device__ float g_Krc   [B_ * H_];
__device__ float g_Vrc   [B_ * H_];
__device__ float g_rctx  [B_ * H_];
__device__ float g_relpart[B_ * NH_ * RSEG_ * 34];

// ------------------------- center = mean over L ----------------------------
__global__ void k_center_partial(const float* __restrict__ x) {
    int b = blockIdx.x, c = blockIdx.y, h = threadIdx.x;
    const float* p = x + ((size_t)b * L_ + (size_t)c * 128) * H_ + h;
    float s = 0.0f;
    #pragma unroll 8
    for (int i = 0; i < 128; i++) s += p[(size_t)i * H_];
    g_cpart[(b * 32 + c) * H_ + h] = s;
}

__global__ void k_center_reduce() {
    int b = blockIdx.x, h = threadIdx.x;
    float s = 0.0f;
    #pragma unroll
    for (int c = 0; c < 32; c++) s += g_cpart[(b * 32 + c) * H_ + h];
    g_center[b * H_ + h] = s * (1.0f / (float)L_);
}

// ------------------------- tf32 helpers ------------------------------------
DEV_INLINE unsigned f2tf32(float v) {
    unsigned r;
    asm("cvt.rna.tf32.f32 %0, %1;" : "=r"(r) : "f"(v));
    return r;
}

DEV_INLINE void mma8(float* c,
                     unsigned a0, unsigned a1, unsigned a2, unsigned a3,
                     unsigned b0, unsigned b1) {
    asm volatile(
        "mma.sync.aligned.m16n8k8.row.col.f32.tf32.tf32.f32 "
        "{%0,%1,%2,%3}, {%4,%5,%6,%7}, {%8,%9}, {%0,%1,%2,%3};"
        : "+f"(c[0]), "+f"(c[1]), "+f"(c[2]), "+f"(c[3])
        : "r"(a0), "r"(a1), "r"(a2), "r"(a3), "r"(b0), "r"(b1));
}

// ------------------------- 3xTF32 GEMM (batched over blockIdx.z) -----------
// Y[z] = X[M,256] @ W[z][256,256] + bias[z].  BM=BN=128, BK=8, 256 threads =
// 8 warps 2(m)x4(n); warp tile 64x32 = 4x4 m16n8 fragments.
// acc += Xhi*Whi + Xhi*Wlo + Xlo*Whi  (fp32-equivalent accuracy).
__global__ __launch_bounds__(256) void tgemm256(
    const float* __restrict__ X,
    const float* __restrict__ W0, const float* __restrict__ bias0, float* __restrict__ Y0,
    const float* __restrict__ W1, const float* __restrict__ bias1, float* __restrict__ Y1,
    const float* __restrict__ W2, const float* __restrict__ bias2, float* __restrict__ Y2) {
    __shared__ float As_hi[2][8][132];   // [k][m]
    __shared__ float As_lo[2][8][132];
    __shared__ float Bs_hi[2][8][132];   // [k][n]
    __shared__ float Bs_lo[2][8][132];

    int z = blockIdx.z;
    const float* W    = (z == 0) ? W0    : (z == 1) ? W1    : W2;
    const float* bias = (z == 0) ? bias0 : (z == 1) ? bias1 : bias2;
    float*       Y    = (z == 0) ? Y0    : (z == 1) ? Y1    : Y2;

    int t  = threadIdx.x;
    int rb = blockIdx.y * 128;
    int cb = blockIdx.x * 128;

    int wid  = t >> 5;
    int lane = t & 31;
    int wm = wid & 1;          // 0..1 : 64-row slab
    int wn = wid >> 1;         // 0..3 : 32-col slab
    int g   = lane >> 2;       // groupID 0..7
    int tig = lane & 3;        // thread-in-group 0..3

    // loader mapping
    int ar  = t >> 1;             // X row 0..127
    int ac  = (t & 1) * 4;        // X col group {0,4}
    int bcr = t >> 5;             // W row 0..7
    int bcc = (t & 31) * 4;       // W col group

    const float* ap = X + (size_t)(rb + ar) * 256 + ac;
    const float* bp = W + (size_t)bcr * 256 + cb + bcc;

    float acc[4][4][4];
    #pragma unroll
    for (int mt = 0; mt < 4; mt++)
        #pragma unroll
        for (int nt = 0; nt < 4; nt++)
            #pragma unroll
            for (int i = 0; i < 4; i++) acc[mt][nt][i] = 0.0f;

    // split+store a fetched tile into smem buffer `buf`
    auto stage = [&](int buf, float4 av, float4 bv) {
        float h0 = __uint_as_float(f2tf32(av.x));
        float h1 = __uint_as_float(f2tf32(av.y));
        float h2 = __uint_as_float(f2tf32(av.z));
        float h3 = __uint_as_float(f2tf32(av.w));
        As_hi[buf][ac + 0][ar] = h0;  As_lo[buf][ac + 0][ar] = av.x - h0;
        As_hi[buf][ac + 1][ar] = h1;  As_lo[buf][ac + 1][ar] = av.y - h1;
        As_hi[buf][ac + 2][ar] = h2;  As_lo[buf][ac + 2][ar] = av.z - h2;
        As_hi[buf][ac + 3][ar] = h3;  As_lo[buf][ac + 3][ar] = av.w - h3;
        float k0 = __uint_as_float(f2tf32(bv.x));
        float k1 = __uint_as_float(f2tf32(bv.y));
        float k2 = __uint_as_float(f2tf32(bv.z));
        float k3 = __uint_as_float(f2tf32(bv.w));
        Bs_hi[buf][bcr][bcc + 0] = k0;  Bs_lo[buf][bcr][bcc + 0] = bv.x - k0;
        Bs_hi[buf][bcr][bcc + 1] = k1;  Bs_lo[buf][bcr][bcc + 1] = bv.y - k1;
        Bs_hi[buf][bcr][bcc + 2] = k2;  Bs_lo[buf][bcr][bcc + 2] = bv.z - k2;
        Bs_hi[buf][bcr][bcc + 3] = k3;  Bs_lo[buf][bcr][bcc + 3] = bv.w - k3;
    };

    // prologue: tile 0 -> buffer 0
    stage(0, *(const float4*)(ap), *(const float4*)(bp));
    __syncthreads();

    int cur = 0;
    for (int kt = 0; kt < 256; kt += 8) {
        float4 av, bv;
        const bool more = (kt + 8 < 256);
        if (more) {                       // issue next tile's loads early
            av = *(const float4*)(ap + kt + 8);
            bv = *(const float4*)(bp + (size_t)(kt + 8) * 256);
        }

        // B fragments for this warp's 4 n-tiles
        unsigned bh[4][2], bl[4][2];
        #pragma unroll
        for (int nt = 0; nt < 4; nt++) {
            int nc = wn * 32 + nt * 8 + g;
            bh[nt][0] = __float_as_uint(Bs_hi[cur][tig    ][nc]);
            bh[nt][1] = __float_as_uint(Bs_hi[cur][tig + 4][nc]);
            bl[nt][0] = __float_as_uint(Bs_lo[cur][tig    ][nc]);
            bl[nt][1] = __float_as_uint(Bs_lo[cur][tig + 4][nc]);
        }
        #pragma unroll
        for (int mt = 0; mt < 4; mt++) {
            int mr = wm * 64 + mt * 16 + g;
            unsigned ah0 = __float_as_uint(As_hi[cur][tig    ][mr    ]);
            unsigned ah1 = __float_as_uint(As_hi[cur][tig    ][mr + 8]);
            unsigned ah2 = __float_as_uint(As_hi[cur][tig + 4][mr    ]);
            unsigned ah3 = __float_as_uint(As_hi[cur][tig + 4][mr + 8]);
            unsigned al0 = __float_as_uint(As_lo[cur][tig    ][mr    ]);
            unsigned al1 = __float_as_uint(As_lo[cur][tig    ][mr + 8]);
            unsigned al2 = __float_as_uint(As_lo[cur][tig + 4][mr    ]);
            unsigned al3 = __float_as_uint(As_lo[cur][tig + 4][mr + 8]);
            #pragma unroll
            for (int nt = 0; nt < 4; nt++) {
                mma8(acc[mt][nt], ah0, ah1, ah2, ah3, bh[nt][0], bh[nt][1]);
                mma8(acc[mt][nt], ah0, ah1, ah2, ah3, bl[nt][0], bl[nt][1]);
                mma8(acc[mt][nt], al0, al1, al2, al3, bh[nt][0], bh[nt][1]);
            }
        }

        if (more) {
            int nxt = cur ^ 1;
            stage(nxt, av, bv);
            __syncthreads();
            cur = nxt;
        }
    }

    // epilogue: bias add + store (c0,c1 at row g; c2,c3 at row g+8)
    #pragma unroll
    for (int mt = 0; mt < 4; mt++) {
        int r0 = rb + wm * 64 + mt * 16 + g;
        #pragma unroll
        for (int nt = 0; nt < 4; nt++) {
            int c0 = cb + wn * 32 + nt * 8 + tig * 2;
            float b0 = bias[c0], b1 = bias[c0 + 1];
            float2 v0 = make_float2(acc[mt][nt][0] + b0, acc[mt][nt][1] + b1);
            float2 v1 = make_float2(acc[mt][nt][2] + b0, acc[mt][nt][3] + b1);
            *(float2*)(Y + (size_t)r0 * 256 + c0)       = v0;
            *(float2*)(Y + (size_t)(r0 + 8) * 256 + c0) = v1;
        }
    }
}

// ------------------------- tiny GEMM for 8 rows (batched over y) -----------
__global__ __launch_bounds__(256) void small_proj(
    const float* __restrict__ X,
    const float* __restrict__ W0, const float* __restrict__ b0, float* __restrict__ Y0,
    const float* __restrict__ W1, const float* __restrict__ b1, float* __restrict__ Y1,
    const float* __restrict__ W2, const float* __restrict__ b2, float* __restrict__ Y2) {
    int z = blockIdx.y;
    const float* W  = (z == 0) ? W0 : (z == 1) ? W1 : W2;
    const float* bb = (z == 0) ? b0 : (z == 1) ? b1 : b2;
    float*       Y  = (z == 0) ? Y0 : (z == 1) ? Y1 : Y2;
    __shared__ float xs[256];
    int r = blockIdx.x, n = threadIdx.x;
    xs[n] = X[r * 256 + n];
    __syncthreads();
    float s = bb[n];
    #pragma unroll 8
    for (int k = 0; k < 256; k++) s += xs[k] * W[k * 256 + n];
    Y[r * 256 + n] = s;
}

// ------------------------- sat attention (5 keys / token) ------------------
__global__ __launch_bounds__(256) void k_sat_attn() {
    int t = blockIdx.x;               // token
    int b = t >> 12;
    int l = t & 4095;
    int h = threadIdx.x >> 5;
    int d = threadIdx.x & 31;
    int off = h * HD_ + d;
    size_t base = (size_t)t * H_;
    size_t ibef = ((size_t)(b << 12) | ((l + 1) & 4095)) * H_;
    size_t iaft = ((size_t)(b << 12) | (unsigned)(l == 0 ? 4095 : 0)) * H_;

    float q  = g_Q[base + off];
    float s0 = q * g_K[ibef + off];
    float s1 = q * g_K[base + off];
    float s2 = q * g_K[iaft + off];
    float s3 = q * g_Kx[base + off];
    float s4 = q * g_Kcen[b * H_ + off];
    #pragma unroll
    for (int m = 16; m; m >>= 1) {
        s0 += __shfl_xor_sync(0xffffffffu, s0, m);
        s1 += __shfl_xor_sync(0xffffffffu, s1, m);
        s2 += __shfl_xor_sync(0xffffffffu, s2, m);
        s3 += __shfl_xor_sync(0xffffffffu, s3, m);
        s4 += __shfl_xor_sync(0xffffffffu, s4, m);
    }
    s0 *= SCALE_; s1 *= SCALE_; s2 *= SCALE_; s3 *= SCALE_; s4 *= SCALE_;
    float mx = fmaxf(fmaxf(fmaxf(s0, s1), fmaxf(s2, s3)), s4);
    float e0 = expf(s0 - mx), e1 = expf(s1 - mx), e2 = expf(s2 - mx);
    float e3 = expf(s3 - mx), e4 = expf(s4 - mx);
    float inv = 1.0f / (e0 + e1 + e2 + e3 + e4);
    float v = e0 * g_V[ibef + off] + e1 * g_V[base + off] + e2 * g_V[iaft + off]
            + e3 * g_Vx[base + off] + e4 * g_Vcen[b * H_ + off];
    g_ctx[base + off] = v * inv;
}

// ------------------------- block reduction helper --------------------------
DEV_INLINE float blockSum256(float v, float* red) {
    #pragma unroll
    for (int m = 16; m; m >>= 1) v += __shfl_xor_sync(0xffffffffu, v, m);
    if ((threadIdx.x & 31) == 0) red[threadIdx.x >> 5] = v;
    __syncthreads();
    float s = red[0] + red[1] + red[2] + red[3] + red[4] + red[5] + red[6] + red[7];
    __syncthreads();
    return s;
}

// ------------------------- sat epilogue: +res, relu, LN --------------------
__global__ __launch_bounds__(256) void k_sat_ln(
    const float* __restrict__ lw, const float* __restrict__ lb,
    float* __restrict__ outp) {
    __shared__ float red[8];
    size_t idx = (size_t)blockIdx.x * H_ + threadIdx.x;
    float v = g_tmp[idx] + g_cur[idx];     // bias already added in GEMM
    v = fmaxf(v, 0.0f);
    float u = blockSum256(v, red) * (1.0f / 256.0f);
    float dv = v - u;
    float var = blockSum256(dv * dv, red) * (1.0f / 256.0f);
    float o = lw[threadIdx.x] * dv * rsqrtf(var + LN_EPS_) + lb[threadIdx.x];
    g_cur[idx] = o;
    if (outp) outp[idx] = o;
}

// ------------------------- rel attention: segmented online softmax ---------
__global__ __launch_bounds__(128) void k_rel_part() {
    int bh = blockIdx.x;                  // 0..63
    int seg = blockIdx.y;                 // 0..15
    int b = bh >> 3, h = bh & 7;
    int tid = threadIdx.x;
    __shared__ float qs[32];
    __shared__ float sm_m[128], sm_s[128];
    __shared__ float sm_acc[128][33];
    if (tid < 32) qs[tid] = g_Qr[b * H_ + h * HD_ + tid];
    __syncthreads();

    float m = -1e30f, s = 0.0f;
    float acc[32];
    #pragma unroll
    for (int d = 0; d < 32; d++) acc[d] = 0.0f;

    int j0 = seg * SEGLEN_;
    int j1 = j0 + SEGLEN_; if (j1 > L_ + 1) j1 = L_ + 1;
    for (int j = j0 + tid; j < j1; j += 128) {
        const float *kp, *vp;
        if (j == 0) {
            kp = g_Krc + b * H_ + h * HD_;
            vp = g_Vrc + b * H_ + h * HD_;
        } else {
            size_t ro = ((size_t)b * L_ + (j - 1)) * H_ + h * HD_;
            kp = g_K + ro; vp = g_V + ro;
        }
        float dot = 0.0f;
        #pragma unroll
        for (int d = 0; d < 32; d += 4) {
            float4 kv = *(const float4*)(kp + d);
            dot += kv.x * qs[d] + kv.y * qs[d + 1] + kv.z * qs[d + 2] + kv.w * qs[d + 3];
        }
        dot *= SCALE_;
        float nm = fmaxf(m, dot);
        float fo = expf(m - nm);
        float p  = expf(dot - nm);
        s = s * fo + p;
        #pragma unroll
        for (int d = 0; d < 32; d += 4) {
            float4 vv = *(const float4*)(vp + d);
            acc[d]     = acc[d]     * fo + p * vv.x;
            acc[d + 1] = acc[d + 1] * fo + p * vv.y;
            acc[d + 2] = acc[d + 2] * fo + p * vv.z;
            acc[d + 3] = acc[d + 3] * fo + p * vv.w;
        }
        m = nm;
    }
    sm_m[tid] = m; sm_s[tid] = s;
    #pragma unroll
    for (int d = 0; d < 32; d++) sm_acc[tid][d] = acc[d];
    __syncthreads();
    for (int str = 64; str >= 1; str >>= 1) {
        if (tid < str) {
            float m1 = sm_m[tid], m2 = sm_m[tid + str];
            float nm = fmaxf(m1, m2);
            float f1 = expf(m1 - nm), f2 = expf(m2 - nm);
            sm_s[tid] = sm_s[tid] * f1 + sm_s[tid + str] * f2;
            #pragma unroll
            for (int d = 0; d < 32; d++)
                sm_acc[tid][d] = sm_acc[tid][d] * f1 + sm_acc[tid + str][d] * f2;
            sm_m[tid] = nm;
        }
        __syncthreads();
    }
    float* op = g_relpart + (size_t)(bh * RSEG_ + seg) * 34;
    if (tid == 0) { op[0] = sm_m[0]; op[1] = sm_s[0]; }
    if (tid < 32) op[2 + tid] = sm_acc[0][tid];
}

__global__ __launch_bounds__(32) void k_rel_combine() {
    int bh = blockIdx.x;
    int d = threadIdx.x;
    float m = -1e30f, s = 0.0f, a = 0.0f;
    #pragma unroll
    for (int seg = 0; seg < RSEG_; seg++) {
        const float* p = g_relpart + (size_t)(bh * RSEG_ + seg) * 34;
        float m2 = p[0], s2 = p[1], a2 = p[2 + d];
        float nm = fmaxf(m, m2);
        float f1 = expf(m - nm), f2 = expf(m2 - nm);
        s = s * f1 + s2 * f2;
        a = a * f1 + a2 * f2;
        m = nm;
    }
    int b = bh >> 3, h = bh & 7;
    g_rctx[b * H_ + h * HD_ + d] = a / s;
}

// ------------------------- rel epilogue: proj + res + relu + LN ------------
__global__ __launch_bounds__(256) void k_rel_out(
    const float* __restrict__ Wo, const float* __restrict__ bo,
    const float* __restrict__ lw, const float* __restrict__ lb,
    float* __restrict__ outp) {
    __shared__ float xs[256];
    __shared__ float red[8];
    int b = blockIdx.x, n = threadIdx.x;
    xs[n] = g_rctx[b * 256 + n];
    __syncthreads();
    float v = bo[n] + g_center[b * 256 + n];
    #pragma unroll 8
    for (int k = 0; k < 256; k++) v += xs[k] * Wo[k * 256 + n];
    v = fmaxf(v, 0.0f);
    float u = blockSum256(v, red) * (1.0f / 256.0f);
    float dv = v - u;
    float var = blockSum256(dv * dv, red) * (1.0f / 256.0f);
    float o = lw[n] * dv * rsqrtf(var + LN_EPS_) + lb[n];
    g_center[b * 256 + n] = o;
    if (outp) outp[b * 256 + n] = o;
}

// ---------------------------------------------------------------------------
extern "C" void kernel_launch(void* const* d_in, const int* in_sizes, int n_in,
                              void* d_out, int out_size) {
    (void)in_sizes; (void)n_in; (void)out_size;
    const float* x      = (const float*)d_in[0];
    const float* sat_Wq = (const float*)d_in[1];
    const float* sat_bq = (const float*)d_in[2];
    const float* sat_Wk = (const float*)d_in[3];
    const float* sat_bk = (const float*)d_in[4];
    const float* sat_Wv = (const float*)d_in[5];
    const float* sat_bv = (const float*)d_in[6];
    const float* sat_Wo = (const float*)d_in[7];
    const float* sat_bo = (const float*)d_in[8];
    const float* rel_Wq = (const float*)d_in[9];
    const float* rel_bq = (const float*)d_in[10];
    const float* rel_Wk = (const float*)d_in[11];
    const float* rel_bk = (const float*)d_in[12];
    const float* rel_Wv = (const float*)d_in[13];
    const float* rel_bv = (const float*)d_in[14];
    const float* rel_Wo = (const float*)d_in[15];
    const float* rel_bo = (const float*)d_in[16];
    const float* sat_ln_w = (const float*)d_in[17];
    const float* sat_ln_b = (const float*)d_in[18];
    const float* rel_ln_w = (const float*)d_in[19];
    const float* rel_ln_b = (const float*)d_in[20];
    float* out = (float*)d_out;

    float *p_cur, *p_Kx, *p_Vx, *p_Q, *p_K, *p_V, *p_ctx, *p_tmp;
    float *p_center, *p_Kcen, *p_Vcen, *p_Qr, *p_Krc, *p_Vrc;
    cudaGetSymbolAddress((void**)&p_cur,  g_cur);
    cudaGetSymbolAddress((void**)&p_Kx,   g_Kx);
    cudaGetSymbolAddress((void**)&p_Vx,   g_Vx);
    cudaGetSymbolAddress((void**)&p_Q,    g_Q);
    cudaGetSymbolAddress((void**)&p_K,    g_K);
    cudaGetSymbolAddress((void**)&p_V,    g_V);
    cudaGetSymbolAddress((void**)&p_ctx,  g_ctx);
    cudaGetSymbolAddress((void**)&p_tmp,  g_tmp);
    cudaGetSymbolAddress((void**)&p_center, g_center);
    cudaGetSymbolAddress((void**)&p_Kcen, g_Kcen);
    cudaGetSymbolAddress((void**)&p_Vcen, g_Vcen);
    cudaGetSymbolAddress((void**)&p_Qr,   g_Qr);
    cudaGetSymbolAddress((void**)&p_Krc,  g_Krc);
    cudaGetSymbolAddress((void**)&p_Vrc,  g_Vrc);

    const dim3 gG1(2, M_ / 128, 1);
    const dim3 gG2(2, M_ / 128, 2);
    const dim3 gG3(2, M_ / 128, 3);

    // cur = x
    cudaMemcpyAsync(p_cur, x, (size_t)M_ * H_ * sizeof(float),
                    cudaMemcpyDeviceToDevice, 0);
    // center = mean_L(x)
    k_center_partial<<<dim3(B_, 32), 256>>>(x);
    k_center_reduce<<<B_, 256>>>();
    // x projections with sat K/V weights (valid for both iterations)
    tgemm256<<<gG2, 256>>>(x,
        sat_Wk, sat_bk, p_Kx,
        sat_Wv, sat_bv, p_Vx,
        sat_Wv, sat_bv, p_Vx);

    for (int it = 0; it < 2; it++) {
        // ---- sat attention ----
        tgemm256<<<gG3, 256>>>(p_cur,
            sat_Wq, sat_bq, p_Q,
            sat_Wk, sat_bk, p_K,
            sat_Wv, sat_bv, p_V);
        small_proj<<<dim3(B_, 2), 256>>>(p_center,
            sat_Wk, sat_bk, p_Kcen,
            sat_Wv, sat_bv, p_Vcen,
            sat_Wv, sat_bv, p_Vcen);
        k_sat_attn<<<M_, 256>>>();
        tgemm256<<<gG1, 256>>>(p_ctx,
            sat_Wo, sat_bo, p_tmp,
            sat_Wo, sat_bo, p_tmp,
            sat_Wo, sat_bo, p_tmp);
        k_sat_ln<<<M_, 256>>>(sat_ln_w, sat_ln_b, it == 1 ? out : (float*)nullptr);

        // ---- rel attention ----
        small_proj<<<dim3(B_, 3), 256>>>(p_center,
            rel_Wq, rel_bq, p_Qr,
            rel_Wk, rel_bk, p_Krc,
            rel_Wv, rel_bv, p_Vrc);
        tgemm256<<<gG2, 256>>>(p_cur,
            rel_Wk, rel_bk, p_K,
            rel_Wv, rel_bv, p_V,
            rel_Wv, rel_bv, p_V);
        k_rel_part<<<dim3(B_ * NH_, RSEG_), 128>>>();
        k_rel_combine<<<B_ * NH_, 32>>>();
        k_rel_out<<<B_, 256>>>(rel_Wo, rel_bo, rel_ln_w, rel_ln_b,
                               it == 1 ? out + (size_t)M_ * H_ : (float*)nullptr);
    }
}